// round 17
// baseline (speedup 1.0000x reference)
#include <cuda_runtime.h>
#include <math.h>

#define BB 4
#define NN 8192
#define NPOINT 409
#define GRES 28
#define NC (GRES*GRES*GRES)
#define CAPR 32
#define CAPU 48
#define FT 512
#define RBLK (BB*NN/FT)     // 64

typedef unsigned long long ull;

__device__ int    g_counts[BB*NC];
__device__ int    g_cstart[BB*(NC+1)];
__device__ int    g_cursor[BB*NC];
__device__ int    g_ptcell[BB*NN];
__device__ int    g_sorted[BB*NN];
__device__ float4 g_pts4[BB*NN];
__device__ float  g_newxyz[BB*NPOINT*3];
__device__ float  g_rep_partial[RBLK];
__device__ float  g_uni_term[BB*NPOINT*5];

struct UniP { float thr[5], el[5], den[5], wgt[5]; int ns[5]; };

#define PK2(out, lo, hi) \
    asm("mov.b64 %0, {%1, %2};" : "=l"(out) : "r"(lo), "r"(hi))
#define UPK2(lo, hi, in) \
    asm("mov.b64 {%0, %1}, %2;" : "=r"(lo), "=r"(hi) : "l"(in))
#define ADD2(out, a, b) \
    asm("add.rn.f32x2 %0, %1, %2;" : "=l"(out) : "l"(a), "l"(b))
#define MUL2(out, a, b) \
    asm("mul.rn.f32x2 %0, %1, %2;" : "=l"(out) : "l"(a), "l"(b))
#define FMA2(out, a, b, c) \
    asm("fma.rn.f32x2 %0, %1, %2, %3;" : "=l"(out) : "l"(a), "l"(b), "l"(c))

__device__ __forceinline__ int cc(float v) {
    int c = (int)floorf((v + 1.0f) * 14.0f);
    return min(max(c, 0), GRES - 1);
}

__global__ void k_zero() {
    int i = blockIdx.x * blockDim.x + threadIdx.x;
    if (i < BB*NC) g_counts[i] = 0;
}

__global__ void k_count(const float* __restrict__ pcd) {
    int gid = blockIdx.x * blockDim.x + threadIdx.x;
    if (gid >= BB*NN) return;
    int b = gid >> 13, i = gid & (NN-1);
    const float* p = pcd + (size_t)b*NN*3 + (size_t)i*3;
    int c = (cc(p[2])*GRES + cc(p[1]))*GRES + cc(p[0]);
    g_ptcell[gid] = c;
    atomicAdd(&g_counts[b*NC + c], 1);
}

__global__ void k_scan() {
    int b = blockIdx.x, t = threadIdx.x;
    const int CPT = (NC + 1023) / 1024;
    int base = t * CPT, s = 0;
    for (int k = 0; k < CPT; k++) { int c = base + k; if (c < NC) s += g_counts[b*NC + c]; }
    __shared__ int sh[1024];
    sh[t] = s; __syncthreads();
    for (int off = 1; off < 1024; off <<= 1) {
        int v = (t >= off) ? sh[t - off] : 0;
        __syncthreads(); sh[t] += v; __syncthreads();
    }
    int run = sh[t] - s;
    for (int k = 0; k < CPT; k++) {
        int c = base + k;
        if (c < NC) {
            g_cstart[b*(NC+1) + c] = run;
            g_cursor[b*NC + c] = run;
            run += g_counts[b*NC + c];
        }
    }
    if (t == 0) g_cstart[b*(NC+1) + NC] = NN;
}

__global__ void k_scatter(const float* __restrict__ pcd) {
    int gid = blockIdx.x * blockDim.x + threadIdx.x;
    if (gid >= BB*NN) return;
    int b = gid >> 13, i = gid & (NN-1);
    int pos = atomicAdd(&g_cursor[b*NC + g_ptcell[gid]], 1);
    g_sorted[b*NN + pos] = i;
    const float* p = pcd + (size_t)b*NN*3 + (size_t)i*3;
    g_pts4[b*NN + pos] = make_float4(p[0], p[1], p[2], 0.0f);
}

__device__ __forceinline__ void ins5(float v, float t5[5]) {
    if (v < t5[4]) {
        t5[4] = v; float x;
        if (t5[4] < t5[3]) { x=t5[3]; t5[3]=t5[4]; t5[4]=x;
        if (t5[3] < t5[2]) { x=t5[2]; t5[2]=t5[3]; t5[3]=x;
        if (t5[2] < t5[1]) { x=t5[1]; t5[1]=t5[2]; t5[2]=x;
        if (t5[1] < t5[0]) { x=t5[0]; t5[0]=t5[1]; t5[1]=x; } } } }
    }
}

__global__ void __launch_bounds__(FT) k_main(const float* __restrict__ pcd,
                                             float thr_rep, float h2) {
    extern __shared__ float4 s4[];       // [NN] (FPS blocks; 128KB)
    __shared__ uint4 shW[2][16];
    __shared__ float sred[16];
    int blk = blockIdx.x, t = threadIdx.x, lane = t & 31, warp = t >> 5;

    if (blk < BB) {
        // ======== FPS with exact top-2 speculation ========
        const float4* G4 = g_pts4 + (size_t)blk*NN;
        for (int k = t; k < NN; k += FT) s4[k] = G4[k];
        __syncthreads();

        ull pxx[8], pyy[8], pzz[8];
        float mind[16];
        #pragma unroll
        for (int k = 0; k < 8; k++) {
            float4 a = s4[t*16 + 2*k], b = s4[t*16 + 2*k + 1];
            PK2(pxx[k], __float_as_uint(a.x), __float_as_uint(b.x));
            PK2(pyy[k], __float_as_uint(a.y), __float_as_uint(b.y));
            PK2(pzz[k], __float_as_uint(a.z), __float_as_uint(b.z));
            mind[2*k] = 1e10f; mind[2*k+1] = 1e10f;
        }
        const float* P = pcd + (size_t)blk*NN*3;
        float4 sA = make_float4(__ldg(P), __ldg(P+1), __ldg(P+2), 0.0f);
        if (t == 0) {
            float* o = &g_newxyz[blk*NPOINT*3];
            o[0]=sA.x; o[1]=sA.y; o[2]=sA.z;
        }

        int it = 1, buf = 0;
        unsigned gi1 = 0, gi2 = 0; float gv2 = 0.0f;
        bool two = false;
        float4 sB = sA;

        for (;;) {
            // ---- update minds with sA (and sB if two) ----
            {
                unsigned nax=__float_as_uint(-sA.x), nay=__float_as_uint(-sA.y), naz=__float_as_uint(-sA.z);
                ull ax2, ay2, az2; PK2(ax2,nax,nax); PK2(ay2,nay,nay); PK2(az2,naz,naz);
                if (two) {
                    unsigned nbx=__float_as_uint(-sB.x), nby=__float_as_uint(-sB.y), nbz=__float_as_uint(-sB.z);
                    ull bx2, by2, bz2; PK2(bx2,nbx,nbx); PK2(by2,nby,nby); PK2(bz2,nbz,nbz);
                    #pragma unroll
                    for (int k = 0; k < 8; k++) {
                        ull dx2, dy2, dz2, da, db;
                        ADD2(dx2, pxx[k], ax2); ADD2(dy2, pyy[k], ay2); ADD2(dz2, pzz[k], az2);
                        MUL2(da, dx2, dx2); FMA2(da, dy2, dy2, da); FMA2(da, dz2, dz2, da);
                        ADD2(dx2, pxx[k], bx2); ADD2(dy2, pyy[k], by2); ADD2(dz2, pzz[k], bz2);
                        MUL2(db, dx2, dx2); FMA2(db, dy2, dy2, db); FMA2(db, dz2, dz2, db);
                        unsigned alo, ahi, blo, bhi;
                        UPK2(alo, ahi, da); UPK2(blo, bhi, db);
                        mind[2*k]   = fminf(mind[2*k],   fminf(__uint_as_float(alo), __uint_as_float(blo)));
                        mind[2*k+1] = fminf(mind[2*k+1], fminf(__uint_as_float(ahi), __uint_as_float(bhi)));
                    }
                } else {
                    #pragma unroll
                    for (int k = 0; k < 8; k++) {
                        ull dx2, dy2, dz2, da;
                        ADD2(dx2, pxx[k], ax2); ADD2(dy2, pyy[k], ay2); ADD2(dz2, pzz[k], az2);
                        MUL2(da, dx2, dx2); FMA2(da, dy2, dy2, da); FMA2(da, dz2, dz2, da);
                        unsigned alo, ahi; UPK2(alo, ahi, da);
                        mind[2*k]   = fminf(mind[2*k],   __uint_as_float(alo));
                        mind[2*k+1] = fminf(mind[2*k+1], __uint_as_float(ahi));
                    }
                }
            }
            // ---- per-thread top-2 (value desc, pos asc) ----
            float v1 = -1.0f, v2 = -1.0f; unsigned p1 = 0, p2 = 0;
            #pragma unroll
            for (int k = 0; k < 16; k++) {
                float m = mind[k]; unsigned pos = (unsigned)(t*16 + k);
                if (m > v1) { v2=v1; p2=p1; v1=m; p1=pos; }
                else if (m > v2) { v2=m; p2=pos; }
            }
            // ---- warp top-2 merge ----
            unsigned u1 = __float_as_uint(v1), u2 = __float_as_uint(v2);
            unsigned w1 = __reduce_max_sync(0xffffffffu, u1);
            unsigned cA = (u1 == w1) ? p1 : 0xffffffffu;
            unsigned wp1 = __reduce_min_sync(0xffffffffu, cA);
            unsigned candv = (p1 == wp1) ? u2 : u1;
            unsigned w2 = __reduce_max_sync(0xffffffffu, candv);
            unsigned cB;
            if (p1 == wp1) cB = (u2 == w2) ? p2 : 0xffffffffu;
            else           cB = (u1 == w2) ? p1 : ((u2 == w2) ? p2 : 0xffffffffu);
            unsigned wp2 = __reduce_min_sync(0xffffffffu, cB);
            if (lane == 0) shW[buf][warp] = make_uint4(w1, wp1, w2, wp2);
            __syncthreads();
            // ---- block top-2 merge (all warps, duplicated lanes) ----
            uint4 wv = shW[buf][lane & 15];
            unsigned b1 = __reduce_max_sync(0xffffffffu, wv.x);
            unsigned cC = (wv.x == b1) ? wv.y : 0xffffffffu;
            gi1 = __reduce_min_sync(0xffffffffu, cC);
            unsigned cdv = (wv.y == gi1) ? wv.z : wv.x;
            unsigned b2 = __reduce_max_sync(0xffffffffu, cdv);
            unsigned cD;
            if (wv.y == gi1) cD = (wv.z == b2) ? wv.w : 0xffffffffu;
            else             cD = (wv.x == b2) ? wv.y : ((wv.z == b2) ? wv.w : 0xffffffffu);
            gi2 = __reduce_min_sync(0xffffffffu, cD);
            gv2 = __uint_as_float(b2);
            buf ^= 1;

            // ---- emit seed(s) ----
            sA = s4[gi1];
            if (t == 0) {
                float* o = &g_newxyz[(blk*NPOINT + it)*3];
                o[0]=sA.x; o[1]=sA.y; o[2]=sA.z;
            }
            it++;
            if (it >= NPOINT) break;
            sB = s4[gi2];
            {
                float ddx = sB.x - sA.x, ddy = sB.y - sA.y, ddz = sB.z - sA.z;
                float dd = ddx*ddx + ddy*ddy + ddz*ddz;
                two = (dd >= gv2 * 1.000001f);
            }
            if (two) {
                if (t == 0) {
                    float* o = &g_newxyz[(blk*NPOINT + it)*3];
                    o[0]=sB.x; o[1]=sB.y; o[2]=sB.z;
                }
                it++;
                if (it >= NPOINT) break;
            }
        }
    } else {
        // -------- repulsion: 1 thread / point --------
        int gid = (blk - BB)*FT + t;
        int b = gid >> 13, i = gid & (NN-1);
        const float*  P  = pcd + (size_t)b*NN*3;
        const float4* S4 = g_pts4 + (size_t)b*NN;
        float xi=P[i*3], yi=P[i*3+1], zi=P[i*3+2];
        int cx=cc(xi), cy=cc(yi), cz=cc(zi);
        int hidx[CAPR]; float hdd[CAPR]; int hn = 0;
        for (int oz=-1; oz<=1; oz++) { int z=cz+oz; if ((unsigned)z>=GRES) continue;
        for (int oy=-1; oy<=1; oy++) { int y=cy+oy; if ((unsigned)y>=GRES) continue;
        for (int ox=-1; ox<=1; ox++) { int x=cx+ox; if ((unsigned)x>=GRES) continue;
            int c=(z*GRES+y)*GRES+x;
            int s0=g_cstart[b*(NC+1)+c], e0=g_cstart[b*(NC+1)+c+1];
            for (int q=s0; q<e0; q++) {
                float4 v = __ldg(&S4[q]);
                float dx=v.x-xi, dy=v.y-yi, dz=v.z-zi;
                float d=dx*dx+dy*dy+dz*dz;
                if (d<=thr_rep && hn<CAPR) { hidx[hn]=g_sorted[b*NN+q]; hdd[hn]=d; hn++; }
            }
        } } }
        for (int a=1; a<hn; a++) {
            int ki=hidx[a]; float kd=hdd[a]; int c2=a-1;
            while (c2>=0 && hidx[c2]>ki) { hidx[c2+1]=hidx[c2]; hdd[c2+1]=hdd[c2]; c2--; }
            hidx[c2+1]=ki; hdd[c2+1]=kd;
        }
        int cnt = hn < 20 ? hn : 20;
        float t5[5] = {1e30f,1e30f,1e30f,1e30f,1e30f};
        for (int a=0; a<cnt; a++) ins5(hdd[a], t5);
        float fd = hdd[0];
        for (int a=cnt; a<20; a++) ins5(fd, t5);
        float csum = 0.0f;
        #pragma unroll
        for (int a=1; a<5; a++) {
            float d5 = fmaxf(t5[a], 0.0f);
            csum += 0.07f - sqrtf(d5)*expf(-d5/h2);
        }
        float v = csum;
        #pragma unroll
        for (int off=16; off; off>>=1) v += __shfl_down_sync(0xffffffffu, v, off);
        if (lane==0) sred[warp]=v;
        __syncthreads();
        if (warp==0) {
            float u = (lane < 16) ? sred[lane] : 0.0f;
            #pragma unroll
            for (int off=16; off; off>>=1) u += __shfl_down_sync(0xffffffffu, u, off);
            if (lane==0) g_rep_partial[blk-BB]=u;
        }
    }
}

__global__ void k_uniform(const float* __restrict__ pcd, UniP up) {
    int q = blockIdx.x * blockDim.x + threadIdx.x;
    if (q >= BB*NPOINT) return;
    int b = q / NPOINT;
    const float4* S4 = g_pts4 + (size_t)b*NN;
    float qx=g_newxyz[q*3], qy=g_newxyz[q*3+1], qz=g_newxyz[q*3+2];
    int cx=cc(qx), cy=cc(qy), cz=cc(qz);
    int cidx[CAPU]; float cd[CAPU], cxr[CAPU], cyr[CAPU], czr[CAPU];
    int cn = 0;
    float thrmax = up.thr[4];
    for (int oz=-2; oz<=2; oz++) { int z=cz+oz; if ((unsigned)z>=GRES) continue;
    for (int oy=-2; oy<=2; oy++) { int y=cy+oy; if ((unsigned)y>=GRES) continue;
    for (int ox=-2; ox<=2; ox++) { int x=cx+ox; if ((unsigned)x>=GRES) continue;
        int c=(z*GRES+y)*GRES+x;
        int s0=g_cstart[b*(NC+1)+c], e0=g_cstart[b*(NC+1)+c+1];
        for (int k=s0; k<e0; k++) {
            float4 v = __ldg(&S4[k]);
            float dx=v.x-qx, dy=v.y-qy, dz=v.z-qz;
            float d=dx*dx+dy*dy+dz*dz;
            if (d<=thrmax && cn<CAPU) {
                cidx[cn]=g_sorted[b*NN+k]; cd[cn]=d;
                cxr[cn]=v.x; cyr[cn]=v.y; czr[cn]=v.z; cn++;
            }
        }
    } } }
    for (int a=1; a<cn; a++) {
        int ki=cidx[a]; float kd=cd[a], kx=cxr[a], ky=cyr[a], kz=czr[a];
        int c2=a-1;
        while (c2>=0 && cidx[c2]>ki) {
            cidx[c2+1]=cidx[c2]; cd[c2+1]=cd[c2];
            cxr[c2+1]=cxr[c2]; cyr[c2+1]=cyr[c2]; czr[c2+1]=czr[c2]; c2--;
        }
        cidx[c2+1]=ki; cd[c2+1]=kd; cxr[c2+1]=kx; cyr[c2+1]=ky; czr[c2+1]=kz;
    }
    for (int pi=0; pi<5; pi++) {
        float thr = up.thr[pi];
        int ns = up.ns[pi];
        int gsel[CAPU]; int gc = 0;
        for (int a=0; a<cn && gc<ns; a++) if (cd[a] <= thr) gsel[gc++] = a;
        int pads = ns - gc;
        float el = up.el[pi], den = up.den[pi];
        float ssum = 0.0f;
        for (int ii=0; ii<gc; ii++) {
            float ud;
            if (pads > 0 && ii == 0) ud = 0.0f;
            else {
                ud = 1e30f;
                int ai = gsel[ii];
                float ax=cxr[ai], ay=cyr[ai], az=czr[ai];
                for (int jj=0; jj<gc; jj++) {
                    if (jj == ii) continue;
                    int aj = gsel[jj];
                    float dx=cxr[aj]-ax, dy=cyr[aj]-ay, dz=czr[aj]-az;
                    ud = fminf(ud, dx*dx+dy*dy+dz*dz);
                }
            }
            float v = sqrtf(fabsf(ud + 1e-8f));
            float tt = v - el;
            ssum += tt*tt/den;
        }
        if (pads > 0) {
            float v = sqrtf(1e-8f);
            float tt = v - el;
            ssum += (float)pads * (tt*tt/den);
        }
        g_uni_term[q*5 + pi] = ssum;
    }
}

__global__ void k_final(float* __restrict__ out, UniP up) {
    __shared__ float sh[256];
    int t = threadIdx.x;
    float uni = 0.0f;
    for (int pi=0; pi<5; pi++) {
        float lo = 0.0f;
        for (int q=t; q<BB*NPOINT; q+=256) lo += g_uni_term[q*5+pi];
        sh[t]=lo; __syncthreads();
        for (int off=128; off; off>>=1) { if (t<off) sh[t]+=sh[t+off]; __syncthreads(); }
        if (t==0) uni += (sh[0] / ((float)(BB*NPOINT) * (float)up.ns[pi])) * up.wgt[pi];
        __syncthreads();
    }
    if (t==0) out[0] = uni / 5.0f;
    sh[t] = (t < RBLK) ? g_rep_partial[t] : 0.0f;
    __syncthreads();
    for (int off=128; off; off>>=1) { if (t<off) sh[t]+=sh[t+off]; __syncthreads(); }
    if (t==0) out[1] = sh[0] / (float)(BB*NN*4);
}

extern "C" void kernel_launch(void* const* d_in, const int* in_sizes, int n_in,
                              void* d_out, int out_size) {
    const float* pcd = (const float*)d_in[0];
    float* out = (float*)d_out;
    UniP up;
    const double ps[5] = {0.004, 0.008, 0.01, 0.012, 0.016};
    for (int i=0; i<5; i++) {
        int ns = (int)(8192.0 * ps[i]);
        double r = sqrt(ps[i]);
        double da = M_PI * ps[i] / ns;
        double el = sqrt(2.0 * da / 1.732);
        up.thr[i] = (float)(r*r);
        up.el[i]  = (float)el;
        up.den[i] = (float)(el + 1e-8);
        up.wgt[i] = (float)((ps[i]*100.0)*(ps[i]*100.0));
        up.ns[i]  = ns;
    }
    cudaFuncSetAttribute(k_main, cudaFuncAttributeMaxDynamicSharedMemorySize,
                         NN * (int)sizeof(float4));
    k_zero<<<(BB*NC+255)/256, 256>>>();
    k_count<<<(BB*NN+255)/256, 256>>>(pcd);
    k_scan<<<BB, 1024>>>();
    k_scatter<<<(BB*NN+255)/256, 256>>>(pcd);
    k_main<<<BB+RBLK, FT, NN*sizeof(float4)>>>(pcd, (float)(0.07*0.07), (float)(0.03*0.03));
    k_uniform<<<(BB*NPOINT+255)/256, 256>>>(pcd, up);
    k_final<<<1, 256>>>(out, up);
}